// round 5
// baseline (speedup 1.0000x reference)
#include <cuda_runtime.h>
#include <math.h>

#define BB 64
#define NN 17
#define CC 32
#define HW 4096   // 64*64

#define OFF_J 0           // joints: 64*17*2 = 2176
#define OFF_V 2176        // valid:  64*17   = 1088
#define OFF_K 3264        // new_keys: 64*17*32 = 34816
#define OFF_D 38080       // dist_x4: 64*17*256*256 = 71303168

__device__ float g_wdist[(size_t)BB * NN * HW];

// packed f32x2 helpers — per-lane IEEE identical to scalar __fmul_rn / fmaf
__device__ __forceinline__ float2 fmul2(float2 a, float2 b) {
    float2 d;
    asm("{\n\t.reg .b64 ra,rb,rd;\n\t"
        "mov.b64 ra,{%2,%3};\n\tmov.b64 rb,{%4,%5};\n\t"
        "mul.rn.f32x2 rd, ra, rb;\n\t"
        "mov.b64 {%0,%1}, rd;\n\t}"
        : "=f"(d.x), "=f"(d.y)
        : "f"(a.x), "f"(a.y), "f"(b.x), "f"(b.y));
    return d;
}
__device__ __forceinline__ float2 ffma2(float2 a, float2 b, float2 c) {
    float2 d;
    asm("{\n\t.reg .b64 ra,rb,rc,rd;\n\t"
        "mov.b64 ra,{%2,%3};\n\tmov.b64 rb,{%4,%5};\n\tmov.b64 rc,{%6,%7};\n\t"
        "fma.rn.f32x2 rd, ra, rb, rc;\n\t"
        "mov.b64 {%0,%1}, rd;\n\t}"
        : "=f"(d.x), "=f"(d.y)
        : "f"(a.x), "f"(a.y), "f"(b.x), "f"(b.y), "f"(c.x), "f"(c.y));
    return d;
}

// Analytic weight map (empirically identical to the literal 15-move loop)
__device__ __forceinline__ float weight_at(int x, int y, int kx, int ky) {
    int dx = abs(x - kx), dy = abs(y - ky);
    int m = 0;
    int mc = (dx > 0) ? dx : ((kx == 0 || kx == 63) ? 1 : 0);
    if (mc >= 1 && mc <= 15 && dy <= mc) m = mc;
    int mr = (dy > 0) ? dy : ((ky == 0 || ky == 63) ? 1 : 0);
    if (mr >= 1 && mr <= 15 && dx <= mr && mr > m) m = mr;
    return m ? (0.5f + 0.25f * (float)m) : 10.0f;
}

// ---------------- Kernel A: wdist (B,N,64,64) ----------------
__global__ void __launch_bounds__(512) kA(const float* __restrict__ q,
                                          const float* __restrict__ keys,
                                          const int*   __restrict__ joints) {
    const int b = blockIdx.y;
    const int p = blockIdx.x * 512 + threadIdx.x;
    __shared__ __align__(16) float skey[NN][CC];
    __shared__ float sk2[NN];
    __shared__ int   skx[NN], sky[NN];
    const int t = threadIdx.x;
    // vectorized load of all 544 key floats (136 float4)
    if (t < NN * CC / 4)
        reinterpret_cast<float4*>(skey)[t] =
            reinterpret_cast<const float4*>(keys + b * NN * CC)[t];
    __syncthreads();
    if (t < NN) {
        float s = 0.f;   // mul+add sequential, no fma (XLA-faithful)
        for (int c = 0; c < CC; c++) s = __fadd_rn(s, __fmul_rn(skey[t][c], skey[t][c]));
        sk2[t] = s;
        skx[t] = joints[(b * NN + t) * 2 + 0];
        sky[t] = joints[(b * NN + t) * 2 + 1];
    }
    __syncthreads();

    float qv[CC];
    const float* qb = q + (size_t)b * CC * HW + p;
    float q2 = 0.f;
#pragma unroll
    for (int c = 0; c < CC; c++) {
        qv[c] = qb[(size_t)c * HW];
        q2 = __fadd_rn(q2, __fmul_rn(qv[c], qv[c]));
    }

    const int y = p >> 6, x = p & 63;
    float* wout = g_wdist + ((size_t)b * NN) * HW + p;
#pragma unroll 1
    for (int n = 0; n < NN; n++) {
        const float4* k4 = reinterpret_cast<const float4*>(skey[n]);
        float dot = 0.f;   // sequential ascending-c fmaf (gemm-faithful)
#pragma unroll
        for (int c4 = 0; c4 < CC / 4; c4++) {
            float4 kk = k4[c4];                       // one LDS.128 broadcast
            dot = fmaf(kk.x, qv[4 * c4 + 0], dot);
            dot = fmaf(kk.y, qv[4 * c4 + 1], dot);
            dot = fmaf(kk.z, qv[4 * c4 + 2], dot);
            dot = fmaf(kk.w, qv[4 * c4 + 3], dot);
        }
        float d2 = __fsub_rn(__fadd_rn(q2, sk2[n]), __fmul_rn(2.0f, dot));
        float dist = sqrtf(fmaxf(d2, 0.0f));
        float wm = weight_at(x, y, skx[n], sky[n]);
        wout[(size_t)n * HW] = __fmul_rn(dist, wm);
    }
}

// ---------------- Kernel B: upsample + argmins + outputs ----------------
__global__ void __launch_bounds__(256) kB(const float* __restrict__ q,
                                          const float* __restrict__ keys,
                                          float* __restrict__ out) {
    const int bn = blockIdx.x;
    const int b  = bn / NN;
    const int t  = threadIdx.x;

    __shared__ float sw[64 * 64];
    __shared__ float rv[256];
    __shared__ int   ri[256];
    __shared__ int   s_idx0, s_valid, s_si;
    __shared__ float s_mind;

    // phase 1: load wdist (streaming), min/argmin (first occurrence)
    const float* src = g_wdist + (size_t)bn * HW;
    float bv = 3.0e38f; int bi = 0;
    for (int k = 0; k < 16; k++) {
        int idx = k * 256 + t;
        float v = __ldcs(src + idx);
        sw[idx] = v;
        if (v < bv) { bv = v; bi = idx; }
    }
    rv[t] = bv; ri[t] = bi;
    __syncthreads();
    for (int s = 128; s > 0; s >>= 1) {
        if (t < s) {
            float v2 = rv[t + s]; int i2 = ri[t + s];
            if (v2 < rv[t] || (v2 == rv[t] && i2 < ri[t])) { rv[t] = v2; ri[t] = i2; }
        }
        __syncthreads();
    }
    if (t == 0) { s_mind = rv[0]; s_idx0 = ri[0]; s_si = 0x7fffffff; }
    __syncthreads();

    // phase 2: 4x bilinear upsample (packed f32x2, bit-exact vs scalar),
    // value-only min tracking; index found by rescan afterwards.
    const float2 wA = make_float2(0.375f, 0.125f);   // lo weights (up / left)
    const float2 wB = make_float2(0.625f, 0.875f);   // hi weights (ce)
    const float2 wC = make_float2(0.875f, 0.625f);   // lo weights (ce)
    const float2 wD = make_float2(0.125f, 0.375f);   // hi weights (dn / right)
    float* od = out + OFF_D + (size_t)bn * 65536;
    float bmin = 3.0e38f;
    for (int it = 0; it < 16; it++) {
        int T = it * 256 + t;
        int ti = T >> 6, tj = T & 63;
        int yU = (ti > 0) ? ti - 1 : 0;
        int yD = (ti < 63) ? ti + 1 : 63;
        int xL = (tj > 0) ? tj - 1 : 0;
        int xR = (tj < 63) ? tj + 1 : 63;

        float2 y01[3], y23[3];
#pragma unroll
        for (int c3 = 0; c3 < 3; c3++) {
            int col = (c3 == 0) ? xL : ((c3 == 1) ? tj : xR);
            float up = sw[yU * 64 + col];
            float ce = sw[ti * 64 + col];
            float dn = sw[yD * 64 + col];
            float2 ce2 = make_float2(ce, ce);
            float2 a = ffma2(wB, ce2, fmul2(wA, make_float2(up, up)));
            float2 bq = ffma2(wD, make_float2(dn, dn), fmul2(wC, ce2));
            if (ti == 0)  a  = ce2;   // exact edge copies (renorm weight = 1)
            if (ti == 63) bq = ce2;
            y01[c3] = a; y23[c3] = bq;
        }
#pragma unroll
        for (int r = 0; r < 4; r++) {
            float vL = (r < 2) ? ((r == 0) ? y01[0].x : y01[0].y)
                               : ((r == 2) ? y23[0].x : y23[0].y);
            float vC = (r < 2) ? ((r == 0) ? y01[1].x : y01[1].y)
                               : ((r == 2) ? y23[1].x : y23[1].y);
            float vR = (r < 2) ? ((r == 0) ? y01[2].x : y01[2].y)
                               : ((r == 2) ? y23[2].x : y23[2].y);
            float2 vC2 = make_float2(vC, vC);
            float2 o01 = ffma2(wB, vC2, fmul2(wA, make_float2(vL, vL)));
            float2 o23 = ffma2(wD, make_float2(vR, vR), fmul2(wC, vC2));
            if (tj == 0)  o01 = vC2;
            if (tj == 63) o23 = vC2;
            int pbase = (4 * ti + r) * 256 + 4 * tj;
            __stcs(reinterpret_cast<float4*>(od + pbase),
                   make_float4(o01.x, o01.y, o23.x, o23.y));
            bmin = fminf(bmin, fminf(fminf(o01.x, o01.y), fminf(o23.x, o23.y)));
        }
    }

    __syncthreads();
    rv[t] = bmin;
    __syncthreads();
    for (int s = 128; s > 0; s >>= 1) {
        if (t < s) rv[t] = fminf(rv[t], rv[t + s]);
        __syncthreads();
    }
    float gmin = rv[0];

    // rescan: only threads owning the min (typically 1) re-read their outputs
    if (bmin == gmin) {
        for (int it = 0; it < 16; it++) {
            int T = it * 256 + t;
            int ti = T >> 6, tj = T & 63;
#pragma unroll
            for (int r = 0; r < 4; r++) {
                int pbase = (4 * ti + r) * 256 + 4 * tj;
                float4 v = *reinterpret_cast<const float4*>(od + pbase);
                if (v.x == gmin) atomicMin(&s_si, pbase);
                if (v.y == gmin) atomicMin(&s_si, pbase + 1);
                if (v.z == gmin) atomicMin(&s_si, pbase + 2);
                if (v.w == gmin) atomicMin(&s_si, pbase + 3);
            }
        }
    }
    __syncthreads();

    if (t == 0) {
        int sidx = s_si;
        bool nonzero = false;
        for (int c = 0; c < CC; c++) nonzero |= (keys[bn * CC + c] != 0.0f);
        bool valid = nonzero && ((int)floorf(s_mind) <= 5);
        s_valid = valid ? 1 : 0;
        int sv = valid ? (sidx >> 8)  : -1;
        int sh = valid ? (sidx & 255) : -1;
        out[OFF_J + bn * 2 + 0] = (float)sv;
        out[OFF_J + bn * 2 + 1] = (float)sh;
        out[OFF_V + bn] = valid ? 1.0f : 0.0f;
    }
    __syncthreads();
    if (t < CC) {
        float nk = s_valid ? q[((size_t)b * CC + t) * HW + s_idx0]
                           : keys[bn * CC + t];
        out[OFF_K + bn * CC + t] = nk;
    }
}

extern "C" void kernel_launch(void* const* d_in, const int* in_sizes, int n_in,
                              void* d_out, int out_size) {
    const float* q      = (const float*)d_in[0];
    const float* keys   = (const float*)d_in[1];
    const int*   joints = (const int*)  d_in[2];
    float* out = (float*)d_out;

    dim3 gA(8, BB);
    kA<<<gA, 512>>>(q, keys, joints);
    kB<<<BB * NN, 256>>>(q, keys, out);
}

// round 6
// speedup vs baseline: 1.0721x; 1.0721x over previous
#include <cuda_runtime.h>
#include <math.h>

#define BB 64
#define NN 17
#define CC 32
#define HW 4096   // 64*64

#define OFF_J 0           // joints: 64*17*2 = 2176
#define OFF_V 2176        // valid:  64*17   = 1088
#define OFF_K 3264        // new_keys: 64*17*32 = 34816
#define OFF_D 38080       // dist_x4: 64*17*256*256 = 71303168

__device__ float g_wdist[(size_t)BB * NN * HW];

// Analytic weight map (empirically identical to the literal 15-move loop)
__device__ __forceinline__ float weight_at(int x, int y, int kx, int ky) {
    int dx = abs(x - kx), dy = abs(y - ky);
    int m = 0;
    int mc = (dx > 0) ? dx : ((kx == 0 || kx == 63) ? 1 : 0);
    if (mc >= 1 && mc <= 15 && dy <= mc) m = mc;
    int mr = (dy > 0) ? dy : ((ky == 0 || ky == 63) ? 1 : 0);
    if (mr >= 1 && mr <= 15 && dx <= mr && mr > m) m = mr;
    return m ? (0.5f + 0.25f * (float)m) : 10.0f;
}

// ---------------- Kernel A: wdist (B,N,64,64) ----------------
__global__ void __launch_bounds__(512) kA(const float* __restrict__ q,
                                          const float* __restrict__ keys,
                                          const int*   __restrict__ joints) {
    const int b = blockIdx.y;
    const int p = blockIdx.x * 512 + threadIdx.x;
    __shared__ __align__(16) float skey[NN][CC];
    __shared__ float sk2[NN];
    __shared__ int   skx[NN], sky[NN];
    const int t = threadIdx.x;
    // vectorized load of all 544 key floats (136 float4)
    if (t < NN * CC / 4)
        reinterpret_cast<float4*>(skey)[t] =
            reinterpret_cast<const float4*>(keys + b * NN * CC)[t];
    __syncthreads();
    if (t < NN) {
        float s = 0.f;   // mul+add sequential, no fma (XLA-faithful)
        for (int c = 0; c < CC; c++) s = __fadd_rn(s, __fmul_rn(skey[t][c], skey[t][c]));
        sk2[t] = s;
        skx[t] = joints[(b * NN + t) * 2 + 0];
        sky[t] = joints[(b * NN + t) * 2 + 1];
    }
    __syncthreads();

    float qv[CC];
    const float* qb = q + (size_t)b * CC * HW + p;
    float q2 = 0.f;
#pragma unroll
    for (int c = 0; c < CC; c++) {
        qv[c] = qb[(size_t)c * HW];
        q2 = __fadd_rn(q2, __fmul_rn(qv[c], qv[c]));
    }

    const int y = p >> 6, x = p & 63;
    float* wout = g_wdist + ((size_t)b * NN) * HW + p;
#pragma unroll 1
    for (int n = 0; n < NN; n++) {
        const float4* k4 = reinterpret_cast<const float4*>(skey[n]);
        float dot = 0.f;   // sequential ascending-c fmaf (gemm-faithful)
#pragma unroll
        for (int c4 = 0; c4 < CC / 4; c4++) {
            float4 kk = k4[c4];                       // one LDS.128 broadcast
            dot = fmaf(kk.x, qv[4 * c4 + 0], dot);
            dot = fmaf(kk.y, qv[4 * c4 + 1], dot);
            dot = fmaf(kk.z, qv[4 * c4 + 2], dot);
            dot = fmaf(kk.w, qv[4 * c4 + 3], dot);
        }
        float d2 = __fsub_rn(__fadd_rn(q2, sk2[n]), __fmul_rn(2.0f, dot));
        float dist = sqrtf(fmaxf(d2, 0.0f));
        float wm = weight_at(x, y, skx[n], sky[n]);
        wout[(size_t)n * HW] = __fmul_rn(dist, wm);
    }
}

// ---------------- Kernel B: upsample + argmins + outputs ----------------
// 8 blocks/SM (256 thr, <=32 regs, 18KB smem) -> 1184 resident >= 1088 grid
// -> SINGLE WAVE. Round-4 structure (inline argmin), strict-< per-thread
// (scan order is index-ascending so first-occurrence is preserved).
__global__ void __launch_bounds__(256, 8) kB(const float* __restrict__ q,
                                             const float* __restrict__ keys,
                                             float* __restrict__ out) {
    const int bn = blockIdx.x;          // b*17+n
    const int b  = bn / NN;
    const int t  = threadIdx.x;

    __shared__ float sw[64 * 64];
    __shared__ float rv[256];
    __shared__ int   ri[256];
    __shared__ int   s_idx0, s_valid;
    __shared__ float s_mind;

    // phase 1: load wdist, track min/argmin (first occurrence)
    const float* src = g_wdist + (size_t)bn * HW;
    float bv = 3.0e38f; int bi = 0;
    for (int k = 0; k < 16; k++) {
        int idx = k * 256 + t;          // ascending per-thread -> strict <
        float v = src[idx];
        sw[idx] = v;
        if (v < bv) { bv = v; bi = idx; }
    }
    rv[t] = bv; ri[t] = bi;
    __syncthreads();
    for (int s = 128; s > 0; s >>= 1) {
        if (t < s) {
            float v2 = rv[t + s]; int i2 = ri[t + s];
            if (v2 < rv[t] || (v2 == rv[t] && i2 < ri[t])) { rv[t] = v2; ri[t] = i2; }
        }
        __syncthreads();
    }
    if (t == 0) { s_mind = rv[0]; s_idx0 = ri[0]; }
    __syncthreads();

    // phase 2: 4x bilinear upsample, gemm-faithful scalar arithmetic:
    //   out = fmaf(w_hi_idx, v_hi_idx, rn(w_lo_idx * v_lo_idx)), ascending idx.
    // y-contraction then x. Clamped edges are exact copies (renorm weight = 1).
    float* od = out + OFF_D + (size_t)bn * 65536;
    float bv2 = 3.0e38f; int bi2 = 0;
    for (int it = 0; it < 16; it++) {
        int T = it * 256 + t;
        int ti = T >> 6, tj = T & 63;
        int yU = (ti > 0) ? ti - 1 : 0;
        int yD = (ti < 63) ? ti + 1 : 63;
        int xL = (tj > 0) ? tj - 1 : 0;
        int xR = (tj < 63) ? tj + 1 : 63;

        float up[3] = { sw[yU * 64 + xL], sw[yU * 64 + tj], sw[yU * 64 + xR] };
        float ce[3] = { sw[ti * 64 + xL], sw[ti * 64 + tj], sw[ti * 64 + xR] };
        float dn[3] = { sw[yD * 64 + xL], sw[yD * 64 + tj], sw[yD * 64 + xR] };

        float vy[4][3];
#pragma unroll
        for (int c3 = 0; c3 < 3; c3++) {
            if (ti == 0) { vy[0][c3] = ce[c3]; vy[1][c3] = ce[c3]; }
            else {
                vy[0][c3] = fmaf(0.625f, ce[c3], __fmul_rn(0.375f, up[c3]));
                vy[1][c3] = fmaf(0.875f, ce[c3], __fmul_rn(0.125f, up[c3]));
            }
            if (ti == 63) { vy[2][c3] = ce[c3]; vy[3][c3] = ce[c3]; }
            else {
                vy[2][c3] = fmaf(0.125f, dn[c3], __fmul_rn(0.875f, ce[c3]));
                vy[3][c3] = fmaf(0.375f, dn[c3], __fmul_rn(0.625f, ce[c3]));
            }
        }
#pragma unroll
        for (int r = 0; r < 4; r++) {
            float vL = vy[r][0], vC = vy[r][1], vR = vy[r][2];
            float o0, o1, o2, o3;
            if (tj == 0) { o0 = vC; o1 = vC; }
            else {
                o0 = fmaf(0.625f, vC, __fmul_rn(0.375f, vL));
                o1 = fmaf(0.875f, vC, __fmul_rn(0.125f, vL));
            }
            if (tj == 63) { o2 = vC; o3 = vC; }
            else {
                o2 = fmaf(0.125f, vR, __fmul_rn(0.875f, vC));
                o3 = fmaf(0.375f, vR, __fmul_rn(0.625f, vC));
            }
            int pbase = (4 * ti + r) * 256 + 4 * tj;
            *reinterpret_cast<float4*>(od + pbase) = make_float4(o0, o1, o2, o3);
            // per-thread visit order is index-ascending: strict < == first occurrence
            if (o0 < bv2) { bv2 = o0; bi2 = pbase; }
            if (o1 < bv2) { bv2 = o1; bi2 = pbase + 1; }
            if (o2 < bv2) { bv2 = o2; bi2 = pbase + 2; }
            if (o3 < bv2) { bv2 = o3; bi2 = pbase + 3; }
        }
    }

    __syncthreads();   // safe reuse of rv/ri
    rv[t] = bv2; ri[t] = bi2;
    __syncthreads();
    for (int s = 128; s > 0; s >>= 1) {
        if (t < s) {
            float v2 = rv[t + s]; int i2 = ri[t + s];
            if (v2 < rv[t] || (v2 == rv[t] && i2 < ri[t])) { rv[t] = v2; ri[t] = i2; }
        }
        __syncthreads();
    }

    if (t == 0) {
        int sidx = ri[0];
        bool nonzero = false;
        for (int c = 0; c < CC; c++) nonzero |= (keys[bn * CC + c] != 0.0f);
        bool valid = nonzero && ((int)floorf(s_mind) <= 5);
        s_valid = valid ? 1 : 0;
        int sv = valid ? (sidx >> 8)  : -1;
        int sh = valid ? (sidx & 255) : -1;
        out[OFF_J + bn * 2 + 0] = (float)sv;
        out[OFF_J + bn * 2 + 1] = (float)sh;
        out[OFF_V + bn] = valid ? 1.0f : 0.0f;
    }
    __syncthreads();
    if (t < CC) {
        float nk = s_valid ? q[((size_t)b * CC + t) * HW + s_idx0]
                           : keys[bn * CC + t];
        out[OFF_K + bn * CC + t] = nk;
    }
}

extern "C" void kernel_launch(void* const* d_in, const int* in_sizes, int n_in,
                              void* d_out, int out_size) {
    const float* q      = (const float*)d_in[0];
    const float* keys   = (const float*)d_in[1];
    const int*   joints = (const int*)  d_in[2];
    float* out = (float*)d_out;

    dim3 gA(8, BB);
    kA<<<gA, 512>>>(q, keys, joints);
    kB<<<BB * NN, 256>>>(q, keys, out);
}